// round 2
// baseline (speedup 1.0000x reference)
#include <cuda_runtime.h>
#include <cstdint>
#include <cstddef>

#define BATCH 16
#define NPTS  8192
#define NSAMP 1024
#define NGRP  32
#define FDIM  64
#define CPB   8          // centroids per MLP block (rows = CPB*32 = 256)

// ---------------- device scratch (no runtime allocation allowed) ----------------
__device__ float g_xs[BATCH][NPTS];
__device__ float g_ys[BATCH][NPTS];
__device__ float g_zs[BATCH][NPTS];
__device__ float g_ss[BATCH][NPTS];
__device__ int   g_fps[BATCH][NSAMP];
__device__ int   g_grp[BATCH][NSAMP][NGRP];

// ---------------- stage 0: SoA + sumsq prep ----------------
__global__ void prep_kernel(const float* __restrict__ xyz) {
    int i = blockIdx.x * blockDim.x + threadIdx.x;
    if (i >= BATCH * NPTS) return;
    int b = i >> 13, n = i & (NPTS - 1);
    float x = xyz[3 * i + 0], y = xyz[3 * i + 1], z = xyz[3 * i + 2];
    g_xs[b][n] = x; g_ys[b][n] = y; g_zs[b][n] = z;
    // contracted form: fma(z,z, fma(y,y, x*x)) to match XLA fp-contraction
    g_ss[b][n] = __fmaf_rn(z, z, __fmaf_rn(y, y, __fmul_rn(x, x)));
}

// ---------------- stage 1: farthest point sampling ----------------
// One block per batch, 1024 threads, 8 points per thread held in registers.
// Argmax key packs (float bits << 13) | (8191 - idx): max key == max dist,
// ties resolve to the smallest index (jnp.argmax semantics).
__global__ __launch_bounds__(1024) void fps_kernel(float* __restrict__ out_sampled) {
    int b = blockIdx.x;
    int t = threadIdx.x;
    int lane = t & 31, warp = t >> 5;
    const float* xs = g_xs[b];
    const float* ys = g_ys[b];
    const float* zs = g_zs[b];

    float px[8], py[8], pz[8], dist[8];
#pragma unroll
    for (int j = 0; j < 8; j++) {
        int p = t + 1024 * j;
        px[j] = xs[p]; py[j] = ys[p]; pz[j] = zs[p];
        dist[j] = 1e10f;
    }

    __shared__ unsigned long long s_wk[32];
    __shared__ int s_far;
    int far = 0;

    for (int k = 0; k < NSAMP; k++) {
        if (t == 0) {
            g_fps[b][k] = far;
            size_t o = ((size_t)b * NSAMP + k) * 3;
            out_sampled[o + 0] = xs[far];
            out_sampled[o + 1] = ys[far];
            out_sampled[o + 2] = zs[far];
        }
        float cx = __ldg(xs + far), cy = __ldg(ys + far), cz = __ldg(zs + far);

        unsigned long long best = 0ull;
#pragma unroll
        for (int j = 0; j < 8; j++) {
            // contracted: fma(dz,dz, fma(dy,dy, dx*dx)) to match XLA
            float dx = __fsub_rn(px[j], cx);
            float dy = __fsub_rn(py[j], cy);
            float dz = __fsub_rn(pz[j], cz);
            float d = __fmaf_rn(dz, dz, __fmaf_rn(dy, dy, __fmul_rn(dx, dx)));
            float dm = fminf(dist[j], d);
            dist[j] = dm;
            unsigned long long key =
                ((unsigned long long)__float_as_uint(dm) << 13) |
                (unsigned)(8191 - (t + 1024 * j));
            best = key > best ? key : best;
        }
#pragma unroll
        for (int o = 16; o > 0; o >>= 1) {
            unsigned long long v = __shfl_xor_sync(0xffffffffu, best, o);
            best = v > best ? v : best;
        }
        if (lane == 0) s_wk[warp] = best;
        __syncthreads();
        if (warp == 0) {
            unsigned long long v = s_wk[lane];
#pragma unroll
            for (int o = 16; o > 0; o >>= 1) {
                unsigned long long u = __shfl_xor_sync(0xffffffffu, v, o);
                v = u > v ? u : v;
            }
            if (lane == 0) s_far = 8191 - (int)(v & 8191ull);
        }
        __syncthreads();
        far = s_far;
    }
}

// ---------------- stage 2: ball query ----------------
// One warp per centroid; scan points in index order, keep first 32 inside radius,
// pad with the first hit. Expanded-sqdist formula to match reference rounding.
__global__ __launch_bounds__(256) void ballq_kernel() {
    int w = threadIdx.x >> 5, lane = threadIdx.x & 31;
    int gs = blockIdx.x * 8 + w;          // global centroid slot
    int b = gs >> 10, s = gs & 1023;

    int far = g_fps[b][s];
    float ax = g_xs[b][far], ay = g_ys[b][far], az = g_zs[b][far];
    float sa = __fmaf_rn(az, az, __fmaf_rn(ay, ay, __fmul_rn(ax, ax)));
    const float RR = 0.04f;

    int filled = 0;
    for (int base = 0; base < NPTS; base += 32) {
        int n = base + lane;
        float bx = g_xs[b][n], by = g_ys[b][n], bz = g_zs[b][n], sb = g_ss[b][n];
        float dot = __fmaf_rn(az, bz, __fmaf_rn(ay, by, __fmul_rn(ax, bx)));
        float sq = __fsub_rn(__fadd_rn(sa, sb), __fmul_rn(2.0f, dot));
        bool inr = !(sq > RR);
        unsigned m = __ballot_sync(0xffffffffu, inr);
        int pos = filled + __popc(m & ((1u << lane) - 1u));
        if (inr && pos < NGRP) g_grp[b][s][pos] = n;
        filled += __popc(m);
        if (filled >= NGRP) break;
    }
    if (filled < NGRP) {
        __syncwarp();
        int first = g_grp[b][s][0];   // centroid itself guarantees >=1 hit
        int j = filled + lane;
        if (j < NGRP) g_grp[b][s][j] = first;
    }
}

// ---------------- stage 3: fused gather + 3-layer MLP + max-pool ----------------
// Block: 256 threads, 8 centroids (256 rows). Activations kept col-major in smem.
// Thread computes an 8x8 register tile; N covered in 64-col passes.
// Shared layout (floats):
//   [0,17152)      sFeat [67][256]   (later overlapped by sH2)
//   [0,32768)      sH2   [128][256]
//   [32768,49152)  sH1   [64][256]   (later: W3 half [128][128])
//   [49152,57344)  sW    (W1 / W2 staging)
__global__ void __launch_bounds__(256, 1) mlp_kernel(
    const float* __restrict__ fea,
    const float* __restrict__ W1, const float* __restrict__ B1,
    const float* __restrict__ W2, const float* __restrict__ B2,
    const float* __restrict__ W3, const float* __restrict__ B3,
    float* __restrict__ out)
{
    extern __shared__ float sm[];
    float* sFeat = sm;
    float* sH2   = sm;
    float* sH1   = sm + 32768;
    float* sW3   = sm + 32768;
    float* sW    = sm + 49152;

    int b  = blockIdx.y;
    int s0 = blockIdx.x * CPB;
    int tid = threadIdx.x;
    int tx = tid & 7, ty = tid >> 3;

    // ---- gather feats (row = tid = c*32+g) + stage W1 ----
    {
        int c = tid >> 5, g = tid & 31;
        int s = s0 + c;
        int far = g_fps[b][s];
        float cx = g_xs[b][far], cy = g_ys[b][far], cz = g_zs[b][far];
        int idx = g_grp[b][s][g];
        sFeat[0 * 256 + tid] = g_xs[b][idx] - cx;
        sFeat[1 * 256 + tid] = g_ys[b][idx] - cy;
        sFeat[2 * 256 + tid] = g_zs[b][idx] - cz;
        const float4* fr = (const float4*)(fea + ((size_t)b * NPTS + idx) * FDIM);
#pragma unroll
        for (int q = 0; q < 16; q++) {
            float4 v = __ldg(fr + q);
            sFeat[(3 + 4 * q + 0) * 256 + tid] = v.x;
            sFeat[(3 + 4 * q + 1) * 256 + tid] = v.y;
            sFeat[(3 + 4 * q + 2) * 256 + tid] = v.z;
            sFeat[(3 + 4 * q + 3) * 256 + tid] = v.w;
        }
        for (int i = tid; i < 1072; i += 256)                 // W1: 4288 floats
            ((float4*)sW)[i] = __ldg(((const float4*)W1) + i);
    }
    __syncthreads();

    float acc[8][8];

    // ---- layer 1: 67 -> 64 ----
    {
#pragma unroll
        for (int i = 0; i < 8; i++)
#pragma unroll
            for (int j = 0; j < 8; j++) acc[i][j] = 0.f;
        for (int k = 0; k < 67; k++) {
            float4 a0 = *(const float4*)&sFeat[k * 256 + ty * 8];
            float4 a1 = *(const float4*)&sFeat[k * 256 + ty * 8 + 4];
            float4 w0 = *(const float4*)&sW[k * 64 + tx * 8];
            float4 w1 = *(const float4*)&sW[k * 64 + tx * 8 + 4];
            float a[8]  = {a0.x, a0.y, a0.z, a0.w, a1.x, a1.y, a1.z, a1.w};
            float bb[8] = {w0.x, w0.y, w0.z, w0.w, w1.x, w1.y, w1.z, w1.w};
#pragma unroll
            for (int i = 0; i < 8; i++)
#pragma unroll
                for (int j = 0; j < 8; j++) acc[i][j] = fmaf(a[i], bb[j], acc[i][j]);
        }
#pragma unroll
        for (int j = 0; j < 8; j++) {
            int col = tx * 8 + j;
            float bias = __ldg(B1 + col);
#pragma unroll
            for (int i = 0; i < 8; i++)
                sH1[col * 256 + ty * 8 + i] = fmaxf(acc[i][j] + bias, 0.f);
        }
    }
    __syncthreads();

    // ---- stage W2 ----
    for (int i = tid; i < 2048; i += 256)                     // W2: 8192 floats
        ((float4*)sW)[i] = __ldg(((const float4*)W2) + i);
    __syncthreads();

    // ---- layer 2: 64 -> 128 (2 passes of 64 cols) ----
    for (int p = 0; p < 2; p++) {
#pragma unroll
        for (int i = 0; i < 8; i++)
#pragma unroll
            for (int j = 0; j < 8; j++) acc[i][j] = 0.f;
        for (int k = 0; k < 64; k++) {
            float4 a0 = *(const float4*)&sH1[k * 256 + ty * 8];
            float4 a1 = *(const float4*)&sH1[k * 256 + ty * 8 + 4];
            float4 w0 = *(const float4*)&sW[k * 128 + p * 64 + tx * 8];
            float4 w1 = *(const float4*)&sW[k * 128 + p * 64 + tx * 8 + 4];
            float a[8]  = {a0.x, a0.y, a0.z, a0.w, a1.x, a1.y, a1.z, a1.w};
            float bb[8] = {w0.x, w0.y, w0.z, w0.w, w1.x, w1.y, w1.z, w1.w};
#pragma unroll
            for (int i = 0; i < 8; i++)
#pragma unroll
                for (int j = 0; j < 8; j++) acc[i][j] = fmaf(a[i], bb[j], acc[i][j]);
        }
#pragma unroll
        for (int j = 0; j < 8; j++) {
            int col = p * 64 + tx * 8 + j;
            float bias = __ldg(B2 + col);
#pragma unroll
            for (int i = 0; i < 8; i++)
                sH2[col * 256 + ty * 8 + i] = fmaxf(acc[i][j] + bias, 0.f);
        }
        if (p == 0) __syncwarp();
    }
    __syncthreads();

    // ---- layer 3: 128 -> 256 (+relu, +max over the 32 group rows) ----
    for (int h = 0; h < 2; h++) {
        // stage W3 columns [h*128, h*128+128) into sW3 [128][128]
        for (int i = tid; i < 4096; i += 256) {
            int r = i >> 5, cq = i & 31;
            ((float4*)sW3)[r * 32 + cq] =
                __ldg((const float4*)(W3 + r * 256 + h * 128) + cq);
        }
        __syncthreads();

        for (int p = 0; p < 2; p++) {
#pragma unroll
            for (int i = 0; i < 8; i++)
#pragma unroll
                for (int j = 0; j < 8; j++) acc[i][j] = 0.f;
            for (int k = 0; k < 128; k++) {
                float4 a0 = *(const float4*)&sH2[k * 256 + ty * 8];
                float4 a1 = *(const float4*)&sH2[k * 256 + ty * 8 + 4];
                float4 w0 = *(const float4*)&sW3[k * 128 + p * 64 + tx * 8];
                float4 w1 = *(const float4*)&sW3[k * 128 + p * 64 + tx * 8 + 4];
                float a[8]  = {a0.x, a0.y, a0.z, a0.w, a1.x, a1.y, a1.z, a1.w};
                float bb[8] = {w0.x, w0.y, w0.z, w0.w, w1.x, w1.y, w1.z, w1.w};
#pragma unroll
                for (int i = 0; i < 8; i++)
#pragma unroll
                    for (int j = 0; j < 8; j++) acc[i][j] = fmaf(a[i], bb[j], acc[i][j]);
            }
            // rows ty*8..ty*8+7 all belong to centroid c = tid>>5 (warp-uniform).
            int c = tid >> 5;
            size_t ob = (size_t)BATCH * NSAMP * 3 +
                        ((size_t)(b * NSAMP + s0 + c)) * 256 + h * 128 + p * 64;
#pragma unroll
            for (int j = 0; j < 8; j++) {
                int col = h * 128 + p * 64 + tx * 8 + j;
                float bias = __ldg(B3 + col);
                float v = 0.f;                 // relu outputs are >= 0
#pragma unroll
                for (int i = 0; i < 8; i++)
                    v = fmaxf(v, fmaxf(acc[i][j] + bias, 0.f));
                v = fmaxf(v, __shfl_xor_sync(0xffffffffu, v, 8));
                v = fmaxf(v, __shfl_xor_sync(0xffffffffu, v, 16));
                if ((ty & 3) == 0) out[ob + tx * 8 + j] = v;
            }
        }
        __syncthreads();   // before restaging sW3 for h=1
    }
}

// ---------------- launcher ----------------
extern "C" void kernel_launch(void* const* d_in, const int* in_sizes, int n_in,
                              void* d_out, int out_size) {
    (void)in_sizes; (void)n_in; (void)out_size;
    const float* xyz = (const float*)d_in[0];
    const float* fea = (const float*)d_in[1];
    const float* W1  = (const float*)d_in[2];
    const float* B1  = (const float*)d_in[3];
    const float* W2  = (const float*)d_in[4];
    const float* B2  = (const float*)d_in[5];
    const float* W3  = (const float*)d_in[6];
    const float* B3  = (const float*)d_in[7];
    float* out = (float*)d_out;

    cudaFuncSetAttribute(mlp_kernel, cudaFuncAttributeMaxDynamicSharedMemorySize,
                         229376);

    prep_kernel<<<(BATCH * NPTS + 255) / 256, 256>>>(xyz);
    fps_kernel<<<BATCH, 1024>>>(out);
    ballq_kernel<<<BATCH * NSAMP / 8, 256>>>();
    dim3 grid(NSAMP / CPB, BATCH);
    mlp_kernel<<<grid, 256, 229376>>>(fea, W1, B1, W2, B2, W3, B3, out);
}

// round 4
// speedup vs baseline: 1.2634x; 1.2634x over previous
#include <cuda_runtime.h>
#include <cuda_bf16.h>
#include <cstdint>
#include <cstddef>

#define BATCH 16
#define NPTS  8192
#define NSAMP 1024
#define NGRP  32
#define FDIM  64

// ---------------- device scratch ----------------
__device__ float g_xs[BATCH][NPTS];
__device__ float g_ys[BATCH][NPTS];
__device__ float g_zs[BATCH][NPTS];
__device__ float g_ss[BATCH][NPTS];
__device__ int   g_fps[BATCH][NSAMP];
__device__ int   g_grp[BATCH][NSAMP][NGRP];

// ---------------- stage 0: SoA + sumsq prep ----------------
__global__ void prep_kernel(const float* __restrict__ xyz) {
    int i = blockIdx.x * blockDim.x + threadIdx.x;
    if (i >= BATCH * NPTS) return;
    int b = i >> 13, n = i & (NPTS - 1);
    float x = xyz[3 * i + 0], y = xyz[3 * i + 1], z = xyz[3 * i + 2];
    g_xs[b][n] = x; g_ys[b][n] = y; g_zs[b][n] = z;
    g_ss[b][n] = __fmaf_rn(z, z, __fmaf_rn(y, y, __fmul_rn(x, x)));
}

// ---------------- stage 1: FPS (unchanged from passing R2) ----------------
__global__ __launch_bounds__(1024) void fps_kernel(float* __restrict__ out_sampled) {
    int b = blockIdx.x;
    int t = threadIdx.x;
    int lane = t & 31, warp = t >> 5;
    const float* xs = g_xs[b];
    const float* ys = g_ys[b];
    const float* zs = g_zs[b];

    float px[8], py[8], pz[8], dist[8];
#pragma unroll
    for (int j = 0; j < 8; j++) {
        int p = t + 1024 * j;
        px[j] = xs[p]; py[j] = ys[p]; pz[j] = zs[p];
        dist[j] = 1e10f;
    }

    __shared__ unsigned long long s_wk[32];
    __shared__ int s_far;
    int far = 0;

    for (int k = 0; k < NSAMP; k++) {
        if (t == 0) {
            g_fps[b][k] = far;
            size_t o = ((size_t)b * NSAMP + k) * 3;
            out_sampled[o + 0] = xs[far];
            out_sampled[o + 1] = ys[far];
            out_sampled[o + 2] = zs[far];
        }
        float cx = __ldg(xs + far), cy = __ldg(ys + far), cz = __ldg(zs + far);

        unsigned long long best = 0ull;
#pragma unroll
        for (int j = 0; j < 8; j++) {
            float dx = __fsub_rn(px[j], cx);
            float dy = __fsub_rn(py[j], cy);
            float dz = __fsub_rn(pz[j], cz);
            float d = __fmaf_rn(dz, dz, __fmaf_rn(dy, dy, __fmul_rn(dx, dx)));
            float dm = fminf(dist[j], d);
            dist[j] = dm;
            unsigned long long key =
                ((unsigned long long)__float_as_uint(dm) << 13) |
                (unsigned)(8191 - (t + 1024 * j));
            best = key > best ? key : best;
        }
#pragma unroll
        for (int o = 16; o > 0; o >>= 1) {
            unsigned long long v = __shfl_xor_sync(0xffffffffu, best, o);
            best = v > best ? v : best;
        }
        if (lane == 0) s_wk[warp] = best;
        __syncthreads();
        if (warp == 0) {
            unsigned long long v = s_wk[lane];
#pragma unroll
            for (int o = 16; o > 0; o >>= 1) {
                unsigned long long u = __shfl_xor_sync(0xffffffffu, v, o);
                v = u > v ? u : v;
            }
            if (lane == 0) s_far = 8191 - (int)(v & 8191ull);
        }
        __syncthreads();
        far = s_far;
    }
}

// ---------------- stage 2: ball query (unchanged) ----------------
__global__ __launch_bounds__(256) void ballq_kernel() {
    int w = threadIdx.x >> 5, lane = threadIdx.x & 31;
    int gs = blockIdx.x * 8 + w;
    int b = gs >> 10, s = gs & 1023;

    int far = g_fps[b][s];
    float ax = g_xs[b][far], ay = g_ys[b][far], az = g_zs[b][far];
    float sa = __fmaf_rn(az, az, __fmaf_rn(ay, ay, __fmul_rn(ax, ax)));
    const float RR = 0.04f;

    int filled = 0;
    for (int base = 0; base < NPTS; base += 32) {
        int n = base + lane;
        float bx = g_xs[b][n], by = g_ys[b][n], bz = g_zs[b][n], sb = g_ss[b][n];
        float dot = __fmaf_rn(az, bz, __fmaf_rn(ay, by, __fmul_rn(ax, bx)));
        float sq = __fsub_rn(__fadd_rn(sa, sb), __fmul_rn(2.0f, dot));
        bool inr = !(sq > RR);
        unsigned m = __ballot_sync(0xffffffffu, inr);
        int pos = filled + __popc(m & ((1u << lane) - 1u));
        if (inr && pos < NGRP) g_grp[b][s][pos] = n;
        filled += __popc(m);
        if (filled >= NGRP) break;
    }
    if (filled < NGRP) {
        __syncwarp();
        int first = g_grp[b][s][0];
        int j = filled + lane;
        if (j < NGRP) g_grp[b][s][j] = first;
    }
}

// =====================================================================
// stage 3: warp-MMA (mma.sync bf16, 3-pass split) fused MLP + maxpool
// Block = 256 threads / 8 warps; warp w owns centroid w (rows 32w..32w+31).
// SMEM (bytes), LDA = 136 bf16 elems (272B row stride, ldmatrix conflict-free):
//   [0,69632)        A hi  [256][136] bf16
//   [69632,139264)   A lo
//   [139264,174080)  W hi  [<=128][136] bf16   (restaged per layer)
//   [174080,208896)  W lo
// =====================================================================
#define LDA       136
#define ABUF_HI   0
#define ABUF_LO   69632
#define WBUF_HI   139264
#define WBUF_LO   174080
#define SMEM_TOT  208896

static __device__ __forceinline__ uint32_t smem_u32(const void* p) {
    uint32_t a;
    asm("{ .reg .u64 t; cvta.to.shared.u64 t, %1; cvt.u32.u64 %0, t; }"
        : "=r"(a) : "l"(p));
    return a;
}
static __device__ __forceinline__ void ldm_x4(uint32_t* r, uint32_t addr) {
    asm volatile("ldmatrix.sync.aligned.m8n8.x4.shared.b16 {%0,%1,%2,%3}, [%4];"
                 : "=r"(r[0]), "=r"(r[1]), "=r"(r[2]), "=r"(r[3]) : "r"(addr));
}
static __device__ __forceinline__ void ldm_x2(uint32_t& r0, uint32_t& r1, uint32_t addr) {
    asm volatile("ldmatrix.sync.aligned.m8n8.x2.shared.b16 {%0,%1}, [%2];"
                 : "=r"(r0), "=r"(r1) : "r"(addr));
}
static __device__ __forceinline__ void mma_bf16(float* c, const uint32_t* a,
                                                uint32_t b0, uint32_t b1) {
    asm volatile(
        "mma.sync.aligned.m16n8k16.row.col.f32.bf16.bf16.f32 "
        "{%0,%1,%2,%3}, {%4,%5,%6,%7}, {%8,%9}, {%0,%1,%2,%3};"
        : "+f"(c[0]), "+f"(c[1]), "+f"(c[2]), "+f"(c[3])
        : "r"(a[0]), "r"(a[1]), "r"(a[2]), "r"(a[3]), "r"(b0), "r"(b1));
}

static __device__ __forceinline__ void split2(float a, float b,
                                              unsigned& hi, unsigned& lo) {
    __nv_bfloat16 ha = __float2bfloat16(a), hb = __float2bfloat16(b);
    float ra = a - __bfloat162float(ha), rb = b - __bfloat162float(hb);
    __nv_bfloat16 la = __float2bfloat16(ra), lb = __float2bfloat16(rb);
    hi = (unsigned)__bfloat16_as_ushort(ha) | ((unsigned)__bfloat16_as_ushort(hb) << 16);
    lo = (unsigned)__bfloat16_as_ushort(la) | ((unsigned)__bfloat16_as_ushort(lb) << 16);
}
// store split pair at (row, even col)
static __device__ __forceinline__ void storeA(char* smp, int row, int col,
                                              float a, float b) {
    unsigned h, l;
    split2(a, b, h, l);
    int off = (row * LDA + col) * 2;
    *(unsigned*)(smp + ABUF_HI + off) = h;
    *(unsigned*)(smp + ABUF_LO + off) = l;
}
// stage weights [K][ldw] row-major -> smem [N][LDA] bf16 hi/lo, K padded to kpad
static __device__ __forceinline__ void stageW(char* smp, const float* W, int K, int N,
                                              int ldw, int kpad, int tid) {
    for (int idx = tid; idx < kpad * N; idx += 256) {
        int k = idx / N, n = idx - k * N;
        float w = (k < K) ? __ldg(W + k * ldw + n) : 0.f;
        __nv_bfloat16 h = __float2bfloat16(w);
        float rr = w - __bfloat162float(h);
        __nv_bfloat16 l = __float2bfloat16(rr);
        int off = (n * LDA + k) * 2;
        *(__nv_bfloat16*)(smp + WBUF_HI + off) = h;
        *(__nv_bfloat16*)(smp + WBUF_LO + off) = l;
    }
}

// warp GEMM: 32 rows x (NBLK*8) cols, 3-pass split, fp32 acc
template <int NBLK>
static __device__ __forceinline__ void warp_gemm(uint32_t sb, int rowBase,
                                                 int ksteps,
                                                 float (&acc)[2][NBLK][4]) {
    int lane = threadIdx.x & 31;
#pragma unroll
    for (int m = 0; m < 2; m++)
#pragma unroll
        for (int nb = 0; nb < NBLK; nb++)
#pragma unroll
            for (int i = 0; i < 4; i++) acc[m][nb][i] = 0.f;

    int arow = lane & 15;
    int acolo = (lane >> 4) << 3;
    int brow = lane & 7;
    int bcolo = lane & 8;

    for (int k = 0; k < ksteps; k++) {
        int k0 = k << 4;
        uint32_t ah[2][4], al[2][4];
#pragma unroll
        for (int m = 0; m < 2; m++) {
            uint32_t ao = (uint32_t)(((rowBase + m * 16 + arow) * LDA + k0 + acolo) * 2);
            ldm_x4(ah[m], sb + ABUF_HI + ao);
            ldm_x4(al[m], sb + ABUF_LO + ao);
        }
#pragma unroll
        for (int nb = 0; nb < NBLK; nb++) {
            uint32_t bo = (uint32_t)(((nb * 8 + brow) * LDA + k0 + bcolo) * 2);
            uint32_t bh0, bh1, bl0, bl1;
            ldm_x2(bh0, bh1, sb + WBUF_HI + bo);
            ldm_x2(bl0, bl1, sb + WBUF_LO + bo);
#pragma unroll
            for (int m = 0; m < 2; m++) {
                mma_bf16(acc[m][nb], ah[m], bh0, bh1);
                mma_bf16(acc[m][nb], ah[m], bl0, bl1);
                mma_bf16(acc[m][nb], al[m], bh0, bh1);
            }
        }
    }
}

// bias + relu + split-store back into A (warp-local rows)
template <int NBLK>
static __device__ __forceinline__ void epi_store(char* smp, int rowBase,
                                                 const float* __restrict__ bias,
                                                 float (&acc)[2][NBLK][4]) {
    int lane = threadIdx.x & 31;
    int cq = (lane & 3) * 2;
    int rq = lane >> 2;
#pragma unroll
    for (int nb = 0; nb < NBLK; nb++) {
        int col = nb * 8 + cq;
        float b0 = __ldg(bias + col), b1 = __ldg(bias + col + 1);
#pragma unroll
        for (int m = 0; m < 2; m++) {
            int row = rowBase + m * 16 + rq;
            float v0 = fmaxf(acc[m][nb][0] + b0, 0.f);
            float v1 = fmaxf(acc[m][nb][1] + b1, 0.f);
            float v2 = fmaxf(acc[m][nb][2] + b0, 0.f);
            float v3 = fmaxf(acc[m][nb][3] + b1, 0.f);
            storeA(smp, row, col, v0, v1);
            storeA(smp, row + 8, col, v2, v3);
        }
    }
}

__global__ void __launch_bounds__(256, 1) mlp_kernel(
    const float* __restrict__ fea,
    const float* __restrict__ W1, const float* __restrict__ B1,
    const float* __restrict__ W2, const float* __restrict__ B2,
    const float* __restrict__ W3, const float* __restrict__ B3,
    float* __restrict__ out)
{
    extern __shared__ char smp[];
    uint32_t sb = smem_u32(smp);
    int tid = threadIdx.x, wid = tid >> 5, lane = tid & 31;
    int b = blockIdx.y, s0 = blockIdx.x * 8;
    int rowBase = wid * 32;

    // ---- gather feats into A (K padded to 80) ----
    {
        int c = tid >> 5, g = tid & 31, s = s0 + c;
        int far = g_fps[b][s];
        float f[80];
        f[0] = g_xs[b][g_grp[b][s][g]] - g_xs[b][far];
        f[1] = g_ys[b][g_grp[b][s][g]] - g_ys[b][far];
        f[2] = g_zs[b][g_grp[b][s][g]] - g_zs[b][far];
        int idx = g_grp[b][s][g];
        const float4* fr = (const float4*)(fea + ((size_t)b * NPTS + idx) * FDIM);
#pragma unroll
        for (int q = 0; q < 16; q++) {
            float4 v = __ldg(fr + q);
            f[3 + 4 * q + 0] = v.x; f[3 + 4 * q + 1] = v.y;
            f[3 + 4 * q + 2] = v.z; f[3 + 4 * q + 3] = v.w;
        }
#pragma unroll
        for (int q = 67; q < 80; q++) f[q] = 0.f;
#pragma unroll
        for (int q = 0; q < 40; q++) storeA(smp, tid, 2 * q, f[2 * q], f[2 * q + 1]);
    }
    // ---- L1: [256x80] @ [80x64] ----
    stageW(smp, W1, 67, 64, 64, 80, tid);
    __syncthreads();
    {
        float acc[2][8][4];
        warp_gemm<8>(sb, rowBase, 5, acc);
        epi_store<8>(smp, rowBase, B1, acc);
    }
    __syncthreads();

    // ---- L2: [256x64] @ [64x128] ----
    stageW(smp, W2, 64, 128, 128, 64, tid);
    __syncthreads();
    {
        float acc[2][16][4];
        warp_gemm<16>(sb, rowBase, 4, acc);
        epi_store<16>(smp, rowBase, B2, acc);
    }
    __syncthreads();

    // ---- L3: [256x128] @ [128x256] in two 128-col halves + maxpool ----
    size_t obase = (size_t)BATCH * NSAMP * 3 +
                   ((size_t)(b * NSAMP + s0 + wid)) * 256;
    for (int nh = 0; nh < 2; nh++) {
        stageW(smp, W3 + nh * 128, 128, 128, 256, 128, tid);
        __syncthreads();
        float acc[2][16][4];
        warp_gemm<16>(sb, rowBase, 8, acc);
        // maxpool over this warp's 32 rows
        int cq = (lane & 3) * 2;
#pragma unroll
        for (int nb = 0; nb < 16; nb++) {
            int col = nh * 128 + nb * 8 + cq;
            float b0 = __ldg(B3 + col), b1 = __ldg(B3 + col + 1);
            float v0 = fmaxf(fmaxf(acc[0][nb][0], acc[0][nb][2]),
                             fmaxf(acc[1][nb][0], acc[1][nb][2])) + b0;
            float v1 = fmaxf(fmaxf(acc[0][nb][1], acc[0][nb][3]),
                             fmaxf(acc[1][nb][1], acc[1][nb][3])) + b1;
            v0 = fmaxf(v0, 0.f); v1 = fmaxf(v1, 0.f);
#pragma unroll
            for (int off = 4; off <= 16; off <<= 1) {
                v0 = fmaxf(v0, __shfl_xor_sync(0xffffffffu, v0, off));
                v1 = fmaxf(v1, __shfl_xor_sync(0xffffffffu, v1, off));
            }
            if (lane < 4) {
                out[obase + col] = v0;
                out[obase + col + 1] = v1;
            }
        }
        if (nh == 0) __syncthreads();
    }
}

// ---------------- launcher ----------------
extern "C" void kernel_launch(void* const* d_in, const int* in_sizes, int n_in,
                              void* d_out, int out_size) {
    (void)in_sizes; (void)n_in; (void)out_size;
    const float* xyz = (const float*)d_in[0];
    const float* fea = (const float*)d_in[1];
    const float* W1  = (const float*)d_in[2];
    const float* B1  = (const float*)d_in[3];
    const float* W2  = (const float*)d_in[4];
    const float* B2  = (const float*)d_in[5];
    const float* W3  = (const float*)d_in[6];
    const float* B3  = (const float*)d_in[7];
    float* out = (float*)d_out;

    cudaFuncSetAttribute(mlp_kernel, cudaFuncAttributeMaxDynamicSharedMemorySize,
                         SMEM_TOT);

    prep_kernel<<<(BATCH * NPTS + 255) / 256, 256>>>(xyz);
    fps_kernel<<<BATCH, 1024>>>(out);
    ballq_kernel<<<BATCH * NSAMP / 8, 256>>>();
    dim3 grid(NSAMP / 8, BATCH);
    mlp_kernel<<<grid, 256, SMEM_TOT>>>(fea, W1, B1, W2, B2, W3, B3, out);
}

// round 5
// speedup vs baseline: 1.7237x; 1.3643x over previous
#include <cuda_runtime.h>
#include <cuda_bf16.h>
#include <cstdint>
#include <cstddef>

#define BATCH 16
#define NPTS  8192
#define NSAMP 1024
#define NGRP  32
#define FDIM  64

// ---------------- device scratch ----------------
__device__ float g_xs[BATCH][NPTS];
__device__ float g_ys[BATCH][NPTS];
__device__ float g_zs[BATCH][NPTS];
__device__ float g_ss[BATCH][NPTS];
__device__ int   g_fps[BATCH][NSAMP];
__device__ int   g_grp[BATCH][NSAMP][NGRP];

// ---------------- stage 0: SoA + sumsq prep ----------------
__global__ void prep_kernel(const float* __restrict__ xyz) {
    int i = blockIdx.x * blockDim.x + threadIdx.x;
    if (i >= BATCH * NPTS) return;
    int b = i >> 13, n = i & (NPTS - 1);
    float x = xyz[3 * i + 0], y = xyz[3 * i + 1], z = xyz[3 * i + 2];
    g_xs[b][n] = x; g_ys[b][n] = y; g_zs[b][n] = z;
    g_ss[b][n] = __fmaf_rn(z, z, __fmaf_rn(y, y, __fmul_rn(x, x)));
}

// ---------------- stage 1: FPS (low-latency iteration) ----------------
// One block per batch, 1024 threads, 8 pts/thread in registers; xyz mirrored
// in dynamic smem so the per-iteration centroid fetch is an LDS broadcast.
// Reductions use REDUX (u32 max on dist bits, then u32 min on tied index);
// per-warp results are double-buffered by iteration parity -> 1 bar/iter.
__global__ __launch_bounds__(1024) void fps_kernel(float* __restrict__ out_sampled) {
    extern __shared__ float sdyn[];
    float* sx = sdyn;
    float* sy = sdyn + NPTS;
    float* sz = sdyn + 2 * NPTS;
    __shared__ uint2 s_wk[2][32];

    int b = blockIdx.x;
    int t = threadIdx.x;
    int lane = t & 31, warp = t >> 5;
    const float* xs = g_xs[b];
    const float* ys = g_ys[b];
    const float* zs = g_zs[b];

    float px[8], py[8], pz[8], dist[8];
#pragma unroll
    for (int j = 0; j < 8; j++) {
        int p = t + 1024 * j;
        float x = xs[p], y = ys[p], z = zs[p];
        px[j] = x; py[j] = y; pz[j] = z;
        sx[p] = x; sy[p] = y; sz[p] = z;
        dist[j] = 1e10f;
    }
    __syncthreads();

    int far = 0;
    for (int k = 0; k < NSAMP; k++) {
        if (t == 0) {
            g_fps[b][k] = far;
            size_t o = ((size_t)b * NSAMP + k) * 3;
            out_sampled[o + 0] = sx[far];
            out_sampled[o + 1] = sy[far];
            out_sampled[o + 2] = sz[far];
        }
        float cx = sx[far], cy = sy[far], cz = sz[far];

        unsigned bd = 0u;
        int bidx = 0;
#pragma unroll
        for (int j = 0; j < 8; j++) {
            float dx = __fsub_rn(px[j], cx);
            float dy = __fsub_rn(py[j], cy);
            float dz = __fsub_rn(pz[j], cz);
            float d = __fmaf_rn(dz, dz, __fmaf_rn(dy, dy, __fmul_rn(dx, dx)));
            float dm = fminf(dist[j], d);
            dist[j] = dm;
            unsigned db = __float_as_uint(dm);   // dm >= 0: u32 order == float order
            if (j == 0) { bd = db; bidx = t; }
            else if (db > bd) { bd = db; bidx = t + 1024 * j; }  // strict > keeps lowest idx
        }
        // warp argmax
        unsigned wmax = __reduce_max_sync(0xffffffffu, bd);
        unsigned cand = (bd == wmax) ? (unsigned)bidx : 0xffffffffu;
        unsigned widx = __reduce_min_sync(0xffffffffu, cand);
        if (lane == 0) s_wk[k & 1][warp] = make_uint2(wmax, widx);
        __syncthreads();
        // every warp reduces the 32 per-warp results (no 2nd barrier needed:
        // next iteration writes the other parity buffer)
        uint2 v = s_wk[k & 1][lane];
        unsigned m2 = __reduce_max_sync(0xffffffffu, v.x);
        unsigned c2 = (v.x == m2) ? v.y : 0xffffffffu;
        far = (int)__reduce_min_sync(0xffffffffu, c2);
    }
}

// ---------------- stage 2: ball query (unchanged) ----------------
__global__ __launch_bounds__(256) void ballq_kernel() {
    int w = threadIdx.x >> 5, lane = threadIdx.x & 31;
    int gs = blockIdx.x * 8 + w;
    int b = gs >> 10, s = gs & 1023;

    int far = g_fps[b][s];
    float ax = g_xs[b][far], ay = g_ys[b][far], az = g_zs[b][far];
    float sa = __fmaf_rn(az, az, __fmaf_rn(ay, ay, __fmul_rn(ax, ax)));
    const float RR = 0.04f;

    int filled = 0;
    for (int base = 0; base < NPTS; base += 32) {
        int n = base + lane;
        float bx = g_xs[b][n], by = g_ys[b][n], bz = g_zs[b][n], sb = g_ss[b][n];
        float dot = __fmaf_rn(az, bz, __fmaf_rn(ay, by, __fmul_rn(ax, bx)));
        float sq = __fsub_rn(__fadd_rn(sa, sb), __fmul_rn(2.0f, dot));
        bool inr = !(sq > RR);
        unsigned m = __ballot_sync(0xffffffffu, inr);
        int pos = filled + __popc(m & ((1u << lane) - 1u));
        if (inr && pos < NGRP) g_grp[b][s][pos] = n;
        filled += __popc(m);
        if (filled >= NGRP) break;
    }
    if (filled < NGRP) {
        __syncwarp();
        int first = g_grp[b][s][0];
        int j = filled + lane;
        if (j < NGRP) g_grp[b][s][j] = first;
    }
}

// =====================================================================
// stage 3: warp-MMA (mma.sync bf16, 3-pass split) fused MLP + maxpool
// (unchanged from R4 passing version)
// =====================================================================
#define LDA       136
#define ABUF_HI   0
#define ABUF_LO   69632
#define WBUF_HI   139264
#define WBUF_LO   174080
#define SMEM_TOT  208896

static __device__ __forceinline__ uint32_t smem_u32(const void* p) {
    uint32_t a;
    asm("{ .reg .u64 t; cvta.to.shared.u64 t, %1; cvt.u32.u64 %0, t; }"
        : "=r"(a) : "l"(p));
    return a;
}
static __device__ __forceinline__ void ldm_x4(uint32_t* r, uint32_t addr) {
    asm volatile("ldmatrix.sync.aligned.m8n8.x4.shared.b16 {%0,%1,%2,%3}, [%4];"
                 : "=r"(r[0]), "=r"(r[1]), "=r"(r[2]), "=r"(r[3]) : "r"(addr));
}
static __device__ __forceinline__ void ldm_x2(uint32_t& r0, uint32_t& r1, uint32_t addr) {
    asm volatile("ldmatrix.sync.aligned.m8n8.x2.shared.b16 {%0,%1}, [%2];"
                 : "=r"(r0), "=r"(r1) : "r"(addr));
}
static __device__ __forceinline__ void mma_bf16(float* c, const uint32_t* a,
                                                uint32_t b0, uint32_t b1) {
    asm volatile(
        "mma.sync.aligned.m16n8k16.row.col.f32.bf16.bf16.f32 "
        "{%0,%1,%2,%3}, {%4,%5,%6,%7}, {%8,%9}, {%0,%1,%2,%3};"
        : "+f"(c[0]), "+f"(c[1]), "+f"(c[2]), "+f"(c[3])
        : "r"(a[0]), "r"(a[1]), "r"(a[2]), "r"(a[3]), "r"(b0), "r"(b1));
}

static __device__ __forceinline__ void split2(float a, float b,
                                              unsigned& hi, unsigned& lo) {
    __nv_bfloat16 ha = __float2bfloat16(a), hb = __float2bfloat16(b);
    float ra = a - __bfloat162float(ha), rb = b - __bfloat162float(hb);
    __nv_bfloat16 la = __float2bfloat16(ra), lb = __float2bfloat16(rb);
    hi = (unsigned)__bfloat16_as_ushort(ha) | ((unsigned)__bfloat16_as_ushort(hb) << 16);
    lo = (unsigned)__bfloat16_as_ushort(la) | ((unsigned)__bfloat16_as_ushort(lb) << 16);
}
static __device__ __forceinline__ void storeA(char* smp, int row, int col,
                                              float a, float b) {
    unsigned h, l;
    split2(a, b, h, l);
    int off = (row * LDA + col) * 2;
    *(unsigned*)(smp + ABUF_HI + off) = h;
    *(unsigned*)(smp + ABUF_LO + off) = l;
}
static __device__ __forceinline__ void stageW(char* smp, const float* W, int K, int N,
                                              int ldw, int kpad, int tid) {
    for (int idx = tid; idx < kpad * N; idx += 256) {
        int k = idx / N, n = idx - k * N;
        float w = (k < K) ? __ldg(W + k * ldw + n) : 0.f;
        __nv_bfloat16 h = __float2bfloat16(w);
        float rr = w - __bfloat162float(h);
        __nv_bfloat16 l = __float2bfloat16(rr);
        int off = (n * LDA + k) * 2;
        *(__nv_bfloat16*)(smp + WBUF_HI + off) = h;
        *(__nv_bfloat16*)(smp + WBUF_LO + off) = l;
    }
}

template <int NBLK>
static __device__ __forceinline__ void warp_gemm(uint32_t sb, int rowBase,
                                                 int ksteps,
                                                 float (&acc)[2][NBLK][4]) {
    int lane = threadIdx.x & 31;
#pragma unroll
    for (int m = 0; m < 2; m++)
#pragma unroll
        for (int nb = 0; nb < NBLK; nb++)
#pragma unroll
            for (int i = 0; i < 4; i++) acc[m][nb][i] = 0.f;

    int arow = lane & 15;
    int acolo = (lane >> 4) << 3;
    int brow = lane & 7;
    int bcolo = lane & 8;

    for (int k = 0; k < ksteps; k++) {
        int k0 = k << 4;
        uint32_t ah[2][4], al[2][4];
#pragma unroll
        for (int m = 0; m < 2; m++) {
            uint32_t ao = (uint32_t)(((rowBase + m * 16 + arow) * LDA + k0 + acolo) * 2);
            ldm_x4(ah[m], sb + ABUF_HI + ao);
            ldm_x4(al[m], sb + ABUF_LO + ao);
        }
#pragma unroll
        for (int nb = 0; nb < NBLK; nb++) {
            uint32_t bo = (uint32_t)(((nb * 8 + brow) * LDA + k0 + bcolo) * 2);
            uint32_t bh0, bh1, bl0, bl1;
            ldm_x2(bh0, bh1, sb + WBUF_HI + bo);
            ldm_x2(bl0, bl1, sb + WBUF_LO + bo);
#pragma unroll
            for (int m = 0; m < 2; m++) {
                mma_bf16(acc[m][nb], ah[m], bh0, bh1);
                mma_bf16(acc[m][nb], ah[m], bl0, bl1);
                mma_bf16(acc[m][nb], al[m], bh0, bh1);
            }
        }
    }
}

template <int NBLK>
static __device__ __forceinline__ void epi_store(char* smp, int rowBase,
                                                 const float* __restrict__ bias,
                                                 float (&acc)[2][NBLK][4]) {
    int lane = threadIdx.x & 31;
    int cq = (lane & 3) * 2;
    int rq = lane >> 2;
#pragma unroll
    for (int nb = 0; nb < NBLK; nb++) {
        int col = nb * 8 + cq;
        float b0 = __ldg(bias + col), b1 = __ldg(bias + col + 1);
#pragma unroll
        for (int m = 0; m < 2; m++) {
            int row = rowBase + m * 16 + rq;
            float v0 = fmaxf(acc[m][nb][0] + b0, 0.f);
            float v1 = fmaxf(acc[m][nb][1] + b1, 0.f);
            float v2 = fmaxf(acc[m][nb][2] + b0, 0.f);
            float v3 = fmaxf(acc[m][nb][3] + b1, 0.f);
            storeA(smp, row, col, v0, v1);
            storeA(smp, row + 8, col, v2, v3);
        }
    }
}

__global__ void __launch_bounds__(256, 1) mlp_kernel(
    const float* __restrict__ fea,
    const float* __restrict__ W1, const float* __restrict__ B1,
    const float* __restrict__ W2, const float* __restrict__ B2,
    const float* __restrict__ W3, const float* __restrict__ B3,
    float* __restrict__ out)
{
    extern __shared__ char smp[];
    uint32_t sb = smem_u32(smp);
    int tid = threadIdx.x, wid = tid >> 5, lane = tid & 31;
    int b = blockIdx.y, s0 = blockIdx.x * 8;
    int rowBase = wid * 32;

    {
        int c = tid >> 5, g = tid & 31, s = s0 + c;
        int far = g_fps[b][s];
        float f[80];
        int idx = g_grp[b][s][g];
        f[0] = g_xs[b][idx] - g_xs[b][far];
        f[1] = g_ys[b][idx] - g_ys[b][far];
        f[2] = g_zs[b][idx] - g_zs[b][far];
        const float4* fr = (const float4*)(fea + ((size_t)b * NPTS + idx) * FDIM);
#pragma unroll
        for (int q = 0; q < 16; q++) {
            float4 v = __ldg(fr + q);
            f[3 + 4 * q + 0] = v.x; f[3 + 4 * q + 1] = v.y;
            f[3 + 4 * q + 2] = v.z; f[3 + 4 * q + 3] = v.w;
        }
#pragma unroll
        for (int q = 67; q < 80; q++) f[q] = 0.f;
#pragma unroll
        for (int q = 0; q < 40; q++) storeA(smp, tid, 2 * q, f[2 * q], f[2 * q + 1]);
    }
    stageW(smp, W1, 67, 64, 64, 80, tid);
    __syncthreads();
    {
        float acc[2][8][4];
        warp_gemm<8>(sb, rowBase, 5, acc);
        epi_store<8>(smp, rowBase, B1, acc);
    }
    __syncthreads();

    stageW(smp, W2, 64, 128, 128, 64, tid);
    __syncthreads();
    {
        float acc[2][16][4];
        warp_gemm<16>(sb, rowBase, 4, acc);
        epi_store<16>(smp, rowBase, B2, acc);
    }
    __syncthreads();

    size_t obase = (size_t)BATCH * NSAMP * 3 +
                   ((size_t)(b * NSAMP + s0 + wid)) * 256;
    for (int nh = 0; nh < 2; nh++) {
        stageW(smp, W3 + nh * 128, 128, 128, 256, 128, tid);
        __syncthreads();
        float acc[2][16][4];
        warp_gemm<16>(sb, rowBase, 8, acc);
        int cq = (lane & 3) * 2;
#pragma unroll
        for (int nb = 0; nb < 16; nb++) {
            int col = nh * 128 + nb * 8 + cq;
            float b0 = __ldg(B3 + col), b1 = __ldg(B3 + col + 1);
            float v0 = fmaxf(fmaxf(acc[0][nb][0], acc[0][nb][2]),
                             fmaxf(acc[1][nb][0], acc[1][nb][2])) + b0;
            float v1 = fmaxf(fmaxf(acc[0][nb][1], acc[0][nb][3]),
                             fmaxf(acc[1][nb][1], acc[1][nb][3])) + b1;
            v0 = fmaxf(v0, 0.f); v1 = fmaxf(v1, 0.f);
#pragma unroll
            for (int off = 4; off <= 16; off <<= 1) {
                v0 = fmaxf(v0, __shfl_xor_sync(0xffffffffu, v0, off));
                v1 = fmaxf(v1, __shfl_xor_sync(0xffffffffu, v1, off));
            }
            if (lane < 4) {
                out[obase + col] = v0;
                out[obase + col + 1] = v1;
            }
        }
        if (nh == 0) __syncthreads();
    }
}

// ---------------- launcher ----------------
extern "C" void kernel_launch(void* const* d_in, const int* in_sizes, int n_in,
                              void* d_out, int out_size) {
    (void)in_sizes; (void)n_in; (void)out_size;
    const float* xyz = (const float*)d_in[0];
    const float* fea = (const float*)d_in[1];
    const float* W1  = (const float*)d_in[2];
    const float* B1  = (const float*)d_in[3];
    const float* W2  = (const float*)d_in[4];
    const float* B2  = (const float*)d_in[5];
    const float* W3  = (const float*)d_in[6];
    const float* B3  = (const float*)d_in[7];
    float* out = (float*)d_out;

    cudaFuncSetAttribute(mlp_kernel, cudaFuncAttributeMaxDynamicSharedMemorySize,
                         SMEM_TOT);
    cudaFuncSetAttribute(fps_kernel, cudaFuncAttributeMaxDynamicSharedMemorySize,
                         3 * NPTS * 4);

    prep_kernel<<<(BATCH * NPTS + 255) / 256, 256>>>(xyz);
    fps_kernel<<<BATCH, 1024, 3 * NPTS * 4>>>(out);
    ballq_kernel<<<BATCH * NSAMP / 8, 256>>>();
    dim3 grid(NSAMP / 8, BATCH);
    mlp_kernel<<<grid, 256, SMEM_TOT>>>(fea, W1, B1, W2, B2, W3, B3, out);
}

// round 6
// speedup vs baseline: 1.8274x; 1.0602x over previous
#include <cuda_runtime.h>
#include <cuda_bf16.h>
#include <cstdint>
#include <cstddef>

#define BATCH 16
#define NPTS  8192
#define NSAMP 1024
#define NGRP  32
#define FDIM  64

// ---------------- device scratch ----------------
__device__ float g_xs[BATCH][NPTS];
__device__ float g_ys[BATCH][NPTS];
__device__ float g_zs[BATCH][NPTS];
__device__ float g_ss[BATCH][NPTS];
__device__ int   g_fps[BATCH][NSAMP];
__device__ int   g_grp[BATCH][NSAMP][NGRP];

// ---------------- stage 0: SoA + sumsq prep ----------------
__global__ void prep_kernel(const float* __restrict__ xyz) {
    int i = blockIdx.x * blockDim.x + threadIdx.x;
    if (i >= BATCH * NPTS) return;
    int b = i >> 13, n = i & (NPTS - 1);
    float x = xyz[3 * i + 0], y = xyz[3 * i + 1], z = xyz[3 * i + 2];
    g_xs[b][n] = x; g_ys[b][n] = y; g_zs[b][n] = z;
    g_ss[b][n] = __fmaf_rn(z, z, __fmaf_rn(y, y, __fmul_rn(x, x)));
}

// ---------------- stage 1: FPS (unchanged from passing R5) ----------------
__global__ __launch_bounds__(1024) void fps_kernel(float* __restrict__ out_sampled) {
    extern __shared__ float sdyn[];
    float* sx = sdyn;
    float* sy = sdyn + NPTS;
    float* sz = sdyn + 2 * NPTS;
    __shared__ uint2 s_wk[2][32];

    int b = blockIdx.x;
    int t = threadIdx.x;
    int lane = t & 31, warp = t >> 5;
    const float* xs = g_xs[b];
    const float* ys = g_ys[b];
    const float* zs = g_zs[b];

    float px[8], py[8], pz[8], dist[8];
#pragma unroll
    for (int j = 0; j < 8; j++) {
        int p = t + 1024 * j;
        float x = xs[p], y = ys[p], z = zs[p];
        px[j] = x; py[j] = y; pz[j] = z;
        sx[p] = x; sy[p] = y; sz[p] = z;
        dist[j] = 1e10f;
    }
    __syncthreads();

    int far = 0;
    for (int k = 0; k < NSAMP; k++) {
        if (t == 0) {
            g_fps[b][k] = far;
            size_t o = ((size_t)b * NSAMP + k) * 3;
            out_sampled[o + 0] = sx[far];
            out_sampled[o + 1] = sy[far];
            out_sampled[o + 2] = sz[far];
        }
        float cx = sx[far], cy = sy[far], cz = sz[far];

        unsigned bd = 0u;
        int bidx = 0;
#pragma unroll
        for (int j = 0; j < 8; j++) {
            float dx = __fsub_rn(px[j], cx);
            float dy = __fsub_rn(py[j], cy);
            float dz = __fsub_rn(pz[j], cz);
            float d = __fmaf_rn(dz, dz, __fmaf_rn(dy, dy, __fmul_rn(dx, dx)));
            float dm = fminf(dist[j], d);
            dist[j] = dm;
            unsigned db = __float_as_uint(dm);
            if (j == 0) { bd = db; bidx = t; }
            else if (db > bd) { bd = db; bidx = t + 1024 * j; }
        }
        unsigned wmax = __reduce_max_sync(0xffffffffu, bd);
        unsigned cand = (bd == wmax) ? (unsigned)bidx : 0xffffffffu;
        unsigned widx = __reduce_min_sync(0xffffffffu, cand);
        if (lane == 0) s_wk[k & 1][warp] = make_uint2(wmax, widx);
        __syncthreads();
        uint2 v = s_wk[k & 1][lane];
        unsigned m2 = __reduce_max_sync(0xffffffffu, v.x);
        unsigned c2 = (v.x == m2) ? v.y : 0xffffffffu;
        far = (int)__reduce_min_sync(0xffffffffu, c2);
    }
}

// ---------------- stage 2: ball query (unchanged) ----------------
__global__ __launch_bounds__(256) void ballq_kernel() {
    int w = threadIdx.x >> 5, lane = threadIdx.x & 31;
    int gs = blockIdx.x * 8 + w;
    int b = gs >> 10, s = gs & 1023;

    int far = g_fps[b][s];
    float ax = g_xs[b][far], ay = g_ys[b][far], az = g_zs[b][far];
    float sa = __fmaf_rn(az, az, __fmaf_rn(ay, ay, __fmul_rn(ax, ax)));
    const float RR = 0.04f;

    int filled = 0;
    for (int base = 0; base < NPTS; base += 32) {
        int n = base + lane;
        float bx = g_xs[b][n], by = g_ys[b][n], bz = g_zs[b][n], sb = g_ss[b][n];
        float dot = __fmaf_rn(az, bz, __fmaf_rn(ay, by, __fmul_rn(ax, bx)));
        float sq = __fsub_rn(__fadd_rn(sa, sb), __fmul_rn(2.0f, dot));
        bool inr = !(sq > RR);
        unsigned m = __ballot_sync(0xffffffffu, inr);
        int pos = filled + __popc(m & ((1u << lane) - 1u));
        if (inr && pos < NGRP) g_grp[b][s][pos] = n;
        filled += __popc(m);
        if (filled >= NGRP) break;
    }
    if (filled < NGRP) {
        __syncwarp();
        int first = g_grp[b][s][0];
        int j = filled + lane;
        if (j < NGRP) g_grp[b][s][j] = first;
    }
}

// =====================================================================
// stage 3: warp-MMA fused MLP + maxpool, occupancy-optimized.
// Block = 256 thr / 8 warps / 4 centroids; warp pair per centroid
// (warp = centroid (wid>>1), N-half (wid&1)).  2 CTAs/SM target:
// smem 106496 B, __launch_bounds__(256,2) caps regs at 128.
// SMEM: A hi [128][136]bf16 @0 (34816), A lo @34816,
//       W hi @69632 (<=18432), W lo @88064 (<=18432).
// W staged per layer: L1 [64][88], L2 [128][72], L3 per 64-col chunk [64][136].
// =====================================================================
#define LDA       136
#define ABUF_HI   0
#define ABUF_LO   34816
#define WBUF_HI   69632
#define WBUF_LO   88064
#define SMEM_TOT  106496

static __device__ __forceinline__ uint32_t smem_u32(const void* p) {
    uint32_t a;
    asm("{ .reg .u64 t; cvta.to.shared.u64 t, %1; cvt.u32.u64 %0, t; }"
        : "=r"(a) : "l"(p));
    return a;
}
static __device__ __forceinline__ void ldm_x4(uint32_t* r, uint32_t addr) {
    asm volatile("ldmatrix.sync.aligned.m8n8.x4.shared.b16 {%0,%1,%2,%3}, [%4];"
                 : "=r"(r[0]), "=r"(r[1]), "=r"(r[2]), "=r"(r[3]) : "r"(addr));
}
static __device__ __forceinline__ void mma_bf16(float* c, const uint32_t* a,
                                                uint32_t b0, uint32_t b1) {
    asm volatile(
        "mma.sync.aligned.m16n8k16.row.col.f32.bf16.bf16.f32 "
        "{%0,%1,%2,%3}, {%4,%5,%6,%7}, {%8,%9}, {%0,%1,%2,%3};"
        : "+f"(c[0]), "+f"(c[1]), "+f"(c[2]), "+f"(c[3])
        : "r"(a[0]), "r"(a[1]), "r"(a[2]), "r"(a[3]), "r"(b0), "r"(b1));
}

static __device__ __forceinline__ void split2(float a, float b,
                                              unsigned& hi, unsigned& lo) {
    __nv_bfloat16 ha = __float2bfloat16(a), hb = __float2bfloat16(b);
    float ra = a - __bfloat162float(ha), rb = b - __bfloat162float(hb);
    __nv_bfloat16 la = __float2bfloat16(ra), lb = __float2bfloat16(rb);
    hi = (unsigned)__bfloat16_as_ushort(ha) | ((unsigned)__bfloat16_as_ushort(hb) << 16);
    lo = (unsigned)__bfloat16_as_ushort(la) | ((unsigned)__bfloat16_as_ushort(lb) << 16);
}
static __device__ __forceinline__ void storeA(char* smp, int row, int col,
                                              float a, float b) {
    unsigned h, l;
    split2(a, b, h, l);
    int off = (row * LDA + col) * 2;
    *(unsigned*)(smp + ABUF_HI + off) = h;
    *(unsigned*)(smp + ABUF_LO + off) = l;
}
// stage weights: src [K][LDSRC] (+srcOff col) -> smem [N][LDWS] bf16 hi/lo
template <int K, int N, int LDSRC, int KPAD, int LDWS>
static __device__ __forceinline__ void stageW(char* smp, const float* W, int srcOff,
                                              int tid0, int nthr) {
    for (int idx = tid0; idx < KPAD * N; idx += nthr) {
        int k = idx / N, n = idx - k * N;
        float w = (k < K) ? __ldg(W + k * LDSRC + srcOff + n) : 0.f;
        __nv_bfloat16 h = __float2bfloat16(w);
        float rr = w - __bfloat162float(h);
        __nv_bfloat16 l = __float2bfloat16(rr);
        int off = (n * LDWS + k) * 2;
        *(__nv_bfloat16*)(smp + WBUF_HI + off) = h;
        *(__nv_bfloat16*)(smp + WBUF_LO + off) = l;
    }
}

// warp GEMM: 32 rows x (NBLK*8) cols from staged W at n-row offset nOff.
// B fragments via paired ldmatrix.x4 (two n8 blocks per load).
template <int NBLK, int KSTEPS, int LDWS>
static __device__ __forceinline__ void warp_gemm(uint32_t sb, int rowBase, int nOff,
                                                 float (&acc)[2][NBLK][4]) {
    int lane = threadIdx.x & 31;
#pragma unroll
    for (int m = 0; m < 2; m++)
#pragma unroll
        for (int nb = 0; nb < NBLK; nb++)
#pragma unroll
            for (int i = 0; i < 4; i++) acc[m][nb][i] = 0.f;

    int arow = lane & 15;
    int acolo = (lane >> 4) << 3;
    int bRow = nOff + ((lane >> 4) & 1) * 8 + (lane & 7);
    int bK = lane & 8;

#pragma unroll
    for (int k = 0; k < KSTEPS; k++) {
        int k0 = k << 4;
        uint32_t ah[2][4], al[2][4];
#pragma unroll
        for (int m = 0; m < 2; m++) {
            uint32_t ao = (uint32_t)(((rowBase + m * 16 + arow) * LDA + k0 + acolo) * 2);
            ldm_x4(ah[m], sb + ABUF_HI + ao);
            ldm_x4(al[m], sb + ABUF_LO + ao);
        }
#pragma unroll
        for (int p = 0; p < NBLK / 2; p++) {
            uint32_t wo = (uint32_t)(((bRow + p * 16) * LDWS + k0 + bK) * 2);
            uint32_t bh[4], bl[4];
            ldm_x4(bh, sb + WBUF_HI + wo);
            ldm_x4(bl, sb + WBUF_LO + wo);
#pragma unroll
            for (int m = 0; m < 2; m++) {
                mma_bf16(acc[m][2 * p],     ah[m], bh[0], bh[1]);
                mma_bf16(acc[m][2 * p],     ah[m], bl[0], bl[1]);
                mma_bf16(acc[m][2 * p],     al[m], bh[0], bh[1]);
                mma_bf16(acc[m][2 * p + 1], ah[m], bh[2], bh[3]);
                mma_bf16(acc[m][2 * p + 1], ah[m], bl[2], bl[3]);
                mma_bf16(acc[m][2 * p + 1], al[m], bh[2], bh[3]);
            }
        }
    }
}

// bias + relu + split-store into A at global activation cols colBase..
template <int NBLK>
static __device__ __forceinline__ void epi_store(char* smp, int rowBase, int colBase,
                                                 const float* __restrict__ bias,
                                                 float (&acc)[2][NBLK][4]) {
    int lane = threadIdx.x & 31;
    int cq = (lane & 3) * 2;
    int rq = lane >> 2;
#pragma unroll
    for (int nb = 0; nb < NBLK; nb++) {
        int col = colBase + nb * 8 + cq;
        float b0 = __ldg(bias + col), b1 = __ldg(bias + col + 1);
#pragma unroll
        for (int m = 0; m < 2; m++) {
            int row = rowBase + m * 16 + rq;
            float v0 = fmaxf(acc[m][nb][0] + b0, 0.f);
            float v1 = fmaxf(acc[m][nb][1] + b1, 0.f);
            float v2 = fmaxf(acc[m][nb][2] + b0, 0.f);
            float v3 = fmaxf(acc[m][nb][3] + b1, 0.f);
            storeA(smp, row, col, v0, v1);
            storeA(smp, row + 8, col, v2, v3);
        }
    }
}

// maxpool epilogue over the warp's 32 rows; writes out cols gcol..gcol+31
static __device__ __forceinline__ void epi_max(int gColBase, const float* __restrict__ B3,
                                               float* __restrict__ out, size_t obase,
                                               float (&acc)[2][4][4]) {
    int lane = threadIdx.x & 31;
    int cq = (lane & 3) * 2;
#pragma unroll
    for (int nb = 0; nb < 4; nb++) {
        int col = gColBase + nb * 8 + cq;
        float b0 = __ldg(B3 + col), b1 = __ldg(B3 + col + 1);
        float v0 = fmaxf(fmaxf(acc[0][nb][0], acc[0][nb][2]),
                         fmaxf(acc[1][nb][0], acc[1][nb][2])) + b0;
        float v1 = fmaxf(fmaxf(acc[0][nb][1], acc[0][nb][3]),
                         fmaxf(acc[1][nb][1], acc[1][nb][3])) + b1;
        v0 = fmaxf(v0, 0.f); v1 = fmaxf(v1, 0.f);
#pragma unroll
        for (int off = 4; off <= 16; off <<= 1) {
            v0 = fmaxf(v0, __shfl_xor_sync(0xffffffffu, v0, off));
            v1 = fmaxf(v1, __shfl_xor_sync(0xffffffffu, v1, off));
        }
        if (lane < 4) {
            out[obase + col] = v0;
            out[obase + col + 1] = v1;
        }
    }
}

__global__ void __launch_bounds__(256, 2) mlp_kernel(
    const float* __restrict__ fea,
    const float* __restrict__ W1, const float* __restrict__ B1,
    const float* __restrict__ W2, const float* __restrict__ B2,
    const float* __restrict__ W3, const float* __restrict__ B3,
    float* __restrict__ out)
{
    extern __shared__ char smp[];
    uint32_t sb = smem_u32(smp);
    int tid = threadIdx.x, wid = tid >> 5;
    int b = blockIdx.y, s0 = blockIdx.x * 4;
    int cent = wid >> 1, nhalf = wid & 1;
    int rowBase = cent * 32;

    // ---- gather feats (threads 0..127, one row each) + stage W1 (128..255) ----
    if (tid < 128) {
        int c = tid >> 5, g = tid & 31, s = s0 + c;
        int far = g_fps[b][s];
        int idx = g_grp[b][s][g];
        float f[80];
        f[0] = g_xs[b][idx] - g_xs[b][far];
        f[1] = g_ys[b][idx] - g_ys[b][far];
        f[2] = g_zs[b][idx] - g_zs[b][far];
        const float4* fr = (const float4*)(fea + ((size_t)b * NPTS + idx) * FDIM);
#pragma unroll
        for (int q = 0; q < 16; q++) {
            float4 v = __ldg(fr + q);
            f[3 + 4 * q + 0] = v.x; f[3 + 4 * q + 1] = v.y;
            f[3 + 4 * q + 2] = v.z; f[3 + 4 * q + 3] = v.w;
        }
#pragma unroll
        for (int q = 67; q < 80; q++) f[q] = 0.f;
#pragma unroll
        for (int q = 0; q < 40; q++) storeA(smp, tid, 2 * q, f[2 * q], f[2 * q + 1]);
    } else {
        stageW<67, 64, 64, 80, 88>(smp, W1, 0, tid - 128, 128);
    }
    __syncthreads();

    // ---- L1: [128x80] @ [80x64]; warp's 32 cols ----
    {
        float acc[2][4][4];
        warp_gemm<4, 5, 88>(sb, rowBase, nhalf * 32, acc);
        __syncthreads();
        epi_store<4>(smp, rowBase, nhalf * 32, B1, acc);
        stageW<64, 128, 128, 64, 72>(smp, W2, 0, tid, 256);
        __syncthreads();
    }

    // ---- L2: [128x64] @ [64x128]; warp's 64 cols ----
    {
        float acc[2][8][4];
        warp_gemm<8, 4, 72>(sb, rowBase, nhalf * 64, acc);
        __syncthreads();
        epi_store<8>(smp, rowBase, nhalf * 64, B2, acc);
        stageW<128, 64, 256, 128, 136>(smp, W3, 0, tid, 256);
        __syncthreads();
    }

    // ---- L3: [128x128] @ [128x256] in four 64-col chunks (2 staged) + maxpool ----
    size_t obase = (size_t)BATCH * NSAMP * 3 +
                   ((size_t)(b * NSAMP + s0 + cent)) * 256;
    {
        float acc[2][4][4];
        warp_gemm<4, 8, 136>(sb, rowBase, nhalf * 32, acc);
        epi_max(nhalf * 32, B3, out, obase, acc);
        __syncthreads();
        stageW<128, 64, 256, 128, 136>(smp, W3, 64, tid, 256);
        __syncthreads();
        warp_gemm<4, 8, 136>(sb, rowBase, nhalf * 32, acc);
        epi_max(64 + nhalf * 32, B3, out, obase, acc);
        __syncthreads();
        stageW<128, 64, 256, 128, 136>(smp, W3, 128, tid, 256);
        __syncthreads();
        warp_gemm<4, 8, 136>(sb, rowBase, nhalf * 32, acc);
        epi_max(128 + nhalf * 32, B3, out, obase, acc);
        __syncthreads();
        stageW<128, 64, 256, 128, 136>(smp, W3, 192, tid, 256);
        __syncthreads();
        warp_gemm<4, 8, 136>(sb, rowBase, nhalf * 32, acc);
        epi_max(192 + nhalf * 32, B3, out, obase, acc);
    }
}

// ---------------- launcher ----------------
extern "C" void kernel_launch(void* const* d_in, const int* in_sizes, int n_in,
                              void* d_out, int out_size) {
    (void)in_sizes; (void)n_in; (void)out_size;
    const float* xyz = (const float*)d_in[0];
    const float* fea = (const float*)d_in[1];
    const float* W1  = (const float*)d_in[2];
    const float* B1  = (const float*)d_in[3];
    const float* W2  = (const float*)d_in[4];
    const float* B2  = (const float*)d_in[5];
    const float* W3  = (const float*)d_in[6];
    const float* B3  = (const float*)d_in[7];
    float* out = (float*)d_out;

    cudaFuncSetAttribute(mlp_kernel, cudaFuncAttributeMaxDynamicSharedMemorySize,
                         SMEM_TOT);
    cudaFuncSetAttribute(fps_kernel, cudaFuncAttributeMaxDynamicSharedMemorySize,
                         3 * NPTS * 4);

    prep_kernel<<<(BATCH * NPTS + 255) / 256, 256>>>(xyz);
    fps_kernel<<<BATCH, 1024, 3 * NPTS * 4>>>(out);
    ballq_kernel<<<BATCH * NSAMP / 8, 256>>>();
    dim3 grid(NSAMP / 4, BATCH);
    mlp_kernel<<<grid, 256, SMEM_TOT>>>(fea, W1, B1, W2, B2, W3, B3, out);
}